// round 2
// baseline (speedup 1.0000x reference)
#include <cuda_runtime.h>
#include <cuda_bf16.h>

// Fixed-shape problem: N=2000 nodes, F=2, HIDDEN=64, K=3, G=256 graphs, E~7998 edges
#define NN    2000
#define EMAX  20000
#define HID   64
#define TPB   512

typedef unsigned long long ull;

// ---------------- f32x2 packed-math helpers (sm_100+ PTX) ----------------
__device__ __forceinline__ ull pk2(float lo, float hi) {
    ull r; asm("mov.b64 %0,{%1,%2};" : "=l"(r) : "f"(lo), "f"(hi)); return r;
}
__device__ __forceinline__ void upk2(ull v, float& lo, float& hi) {
    asm("mov.b64 {%0,%1}, %2;" : "=f"(lo), "=f"(hi) : "l"(v));
}
__device__ __forceinline__ ull fma2v(ull a, ull b, ull c) {
    ull d; asm("fma.rn.f32x2 %0, %1, %2, %3;" : "=l"(d) : "l"(a), "l"(b), "l"(c)); return d;
}

// ---------------- device-global scratch ----------------
__device__ int  g_ptr[NN + 1];    // CSR row pointers (by destination)
__device__ int2 g_edge[EMAX];     // .x = src node, .y = bits of gcn_norm weight

// ---------------- fused prepass: one CTA, smem atomics ----------------
__global__ __launch_bounds__(1024)
void k_pre(const int* __restrict__ row, const int* __restrict__ col,
           const float* __restrict__ ew, int E) {
    __shared__ float sdeg[NN];
    __shared__ int   scnt[NN];
    __shared__ int   sptr[NN + 1];
    __shared__ int   scur[NN];
    __shared__ int   warpsum[32];
    const int t = threadIdx.x;           // 1024 threads

    for (int i = t; i < NN; i += 1024) { sdeg[i] = 0.f; scnt[i] = 0; }
    __syncthreads();

    // weighted degree + per-dest counts (smem atomics)
    for (int e = t; e < E; e += 1024) {
        int c = col[e];
        atomicAdd(&sdeg[c], ew[e]);
        atomicAdd(&scnt[c], 1);
    }
    __syncthreads();

    // exclusive scan of scnt -> sptr / scur / g_ptr
    {
        int i0 = 2 * t, i1 = 2 * t + 1;
        int a0 = (i0 < NN) ? scnt[i0] : 0;
        int a1 = (i1 < NN) ? scnt[i1] : 0;
        int tot = a0 + a1;
        int lane = t & 31, wid = t >> 5;
        int v = tot;
        #pragma unroll
        for (int o = 1; o < 32; o <<= 1) {
            int u = __shfl_up_sync(0xFFFFFFFFu, v, o);
            if (lane >= o) v += u;
        }
        if (lane == 31) warpsum[wid] = v;
        __syncthreads();
        if (wid == 0) {
            int w = warpsum[lane];
            #pragma unroll
            for (int o = 1; o < 32; o <<= 1) {
                int u = __shfl_up_sync(0xFFFFFFFFu, w, o);
                if (lane >= o) w += u;
            }
            warpsum[lane] = w;
        }
        __syncthreads();
        int base = v - tot + (wid ? warpsum[wid - 1] : 0);
        if (i0 < NN) { sptr[i0] = base;      scur[i0] = base;      g_ptr[i0] = base; }
        if (i1 < NN) { sptr[i1] = base + a0; scur[i1] = base + a0; g_ptr[i1] = base + a0; }
        if (t == 0)  { sptr[NN] = E; g_ptr[NN] = E; }
    }
    __syncthreads();

    // scatter edges (CSR by destination) with precomputed gcn_norm weight
    for (int e = t; e < E; e += 1024) {
        int r = row[e], c = col[e];
        float dr = sdeg[r], dc = sdeg[c];
        float ir = (dr > 0.f) ? rsqrtf(dr) : 0.f;
        float ic = (dc > 0.f) ? rsqrtf(dc) : 0.f;
        float nrm = ir * ew[e] * ic;
        int p = atomicAdd(&scur[c], 1);
        g_edge[p] = make_int2(r, __float_as_int(nrm));
    }
}

// ---------------- main fused kernel: one CTA per graph ----------------
// smem (bytes): 6*NN*8 f32x2 buffers | w1q 2048 | w2q 2048 | b1s 256 | sptr (NN+1)*4
#define SMEM_BYTES (6 * NN * 8 + 2048 + 2048 + 256 + (NN + 1) * 4)

__device__ __forceinline__ void gather_hop(const ull* __restrict__ pin,
                                           ull* __restrict__ pout,
                                           const ull* __restrict__ addbuf,
                                           const int* __restrict__ sptr,
                                           int t, int bs) {
    for (int n = t; n < NN; n += bs) {
        int b = sptr[n], e = sptr[n + 1];
        ull acc = addbuf ? addbuf[n] : 0ull;     // 0 bits == (0.f, 0.f)
        for (int q = b; q < e; q++) {
            int2 ed = g_edge[q];
            float w = __int_as_float(ed.y);
            acc = fma2v(pin[ed.x], pk2(w, w), acc);
        }
        pout[n] = acc;
    }
}

__global__ __launch_bounds__(TPB, 2)
void k_main(const float* __restrict__ x,
            const float* __restrict__ W1, const float* __restrict__ b1,
            const float* __restrict__ W2, const float* __restrict__ b2,
            float* __restrict__ out) {
    extern __shared__ float sm[];
    ull* pb0     = (ull*)sm;
    ull* pb1     = pb0 + NN;
    ull* pb2     = pb1 + NN;
    ull* pb3     = pb2 + NN;
    ull* scratch = pb3 + NN;
    ull* xbuf    = scratch + NN;
    float* w1q = (float*)(xbuf + NN);    // [32 jp][8 i][2 half]: (W1cat[i][2jp], W1cat[i][2jp+1])
    float* w2q = w1q + 512;              // [32 jp][2 jj][8 c]: W2cat[2jp+jj][c]
    float* b1s = w2q + 512;              // 64 floats; read pairwise as ull
    int*   sptr = (int*)(b1s + 64);

    const int t  = threadIdx.x;
    const int bs = blockDim.x;
    const int g  = blockIdx.x;

    // stage packed weights
    for (int i = t; i < 512; i += bs) {
        int jp = i >> 4, rem = i & 15;
        {   // w1q: half-interleaved hidden pairs
            int ii = rem >> 1, half = rem & 1;
            w1q[i] = W1[ii * HID + 2 * jp + half];
        }
        {   // w2q: rows j=2jp+jj of W2cat[j][c], c = k*2+o
            int jj = rem >> 3, c = rem & 7;
            int j = 2 * jp + jj;
            w2q[i] = W2[(c >> 1) * (HID * 2) + j * 2 + (c & 1)];
        }
    }
    for (int i = t; i < HID; i += bs) b1s[i] = b1[i];
    for (int i = t; i < NN + 1; i += bs) sptr[i] = g_ptr[i];

    // stage x (node features are contiguous pairs)
    const ull* xg = (const ull*)(x + (size_t)g * 2 * NN);
    for (int n = t; n < NN; n += bs) { ull v = xg[n]; xbuf[n] = v; pb0[n] = v; }
    __syncthreads();

    // layer-1 hops: p_k = A p_{k-1}   (F=2, packed)
    gather_hop(pb0, pb1, nullptr, sptr, t, bs); __syncthreads();
    gather_hop(pb1, pb2, nullptr, sptr, t, bs); __syncthreads();
    gather_hop(pb2, pb3, nullptr, sptr, t, bs); __syncthreads();

    // dense per-node sandwich: [8] -> 64 (relu) -> [8], f32x2 over hidden pairs
    {
        const ulonglong2* w1v = (const ulonglong2*)w1q;   // 4 per jp
        const ulonglong2* w2v = (const ulonglong2*)w2q;   // 4 per jp
        const ull* b1v = (const ull*)b1s;                 // 1 per jp
        for (int n = t; n < NN; n += bs) {
            float f0, f1;
            ull a;
            a = pb0[n]; upk2(a, f0, f1); ull p0 = pk2(f0, f0), p1 = pk2(f1, f1);
            a = pb1[n]; upk2(a, f0, f1); ull p2 = pk2(f0, f0), p3 = pk2(f1, f1);
            a = pb2[n]; upk2(a, f0, f1); ull p4 = pk2(f0, f0), p5 = pk2(f1, f1);
            a = pb3[n]; upk2(a, f0, f1); ull p6 = pk2(f0, f0), p7 = pk2(f1, f1);
            ull m0 = 0, m1 = 0, m2 = 0, m3 = 0;
            #pragma unroll 4
            for (int jp = 0; jp < 32; jp++) {
                ulonglong2 qa = w1v[jp * 4 + 0], qb = w1v[jp * 4 + 1];
                ulonglong2 qc = w1v[jp * 4 + 2], qd = w1v[jp * 4 + 3];
                ull h = b1v[jp];
                h = fma2v(p0, qa.x, h); h = fma2v(p1, qa.y, h);
                h = fma2v(p2, qb.x, h); h = fma2v(p3, qb.y, h);
                h = fma2v(p4, qc.x, h); h = fma2v(p5, qc.y, h);
                h = fma2v(p6, qd.x, h); h = fma2v(p7, qd.y, h);
                float h0, h1; upk2(h, h0, h1);
                h0 = fmaxf(h0, 0.f); h1 = fmaxf(h1, 0.f);
                ull h0p = pk2(h0, h0), h1p = pk2(h1, h1);
                ulonglong2 ra = w2v[jp * 4 + 0], rb = w2v[jp * 4 + 1];
                ulonglong2 rc = w2v[jp * 4 + 2], rd = w2v[jp * 4 + 3];
                m0 = fma2v(h0p, ra.x, m0); m1 = fma2v(h0p, ra.y, m1);
                m2 = fma2v(h0p, rb.x, m2); m3 = fma2v(h0p, rb.y, m3);
                m0 = fma2v(h1p, rc.x, m0); m1 = fma2v(h1p, rc.y, m1);
                m2 = fma2v(h1p, rd.x, m2); m3 = fma2v(h1p, rd.y, m3);
            }
            pb0[n] = m0;   // m0 pair (out ch 0,1 hop 0)
            pb1[n] = m1;   // hop 1
            pb2[n] = m2;   // hop 2
            pb3[n] = m3;   // hop 3
        }
    }
    __syncthreads();

    // layer-2 Horner: out2 = m0 + A(m1 + A(m2 + A m3))
    gather_hop(pb3, scratch, pb2, sptr, t, bs); __syncthreads();  // s = m2 + A m3
    gather_hop(scratch, pb3, pb1, sptr, t, bs); __syncthreads();  // s = m1 + A s

    // final: out = x + m0 + A s + b2
    float b20 = b2[0], b21 = b2[1];
    float2* og = (float2*)out + (size_t)g * NN;
    for (int n = t; n < NN; n += bs) {
        int b = sptr[n], e = sptr[n + 1];
        ull acc = pb0[n];
        for (int q = b; q < e; q++) {
            int2 ed = g_edge[q];
            float w = __int_as_float(ed.y);
            acc = fma2v(pb3[ed.x], pk2(w, w), acc);
        }
        float ox, oy; upk2(acc, ox, oy);
        float xl, xh; upk2(xbuf[n], xl, xh);
        og[n] = make_float2(xl + ox + b20, xh + oy + b21);
    }
}

// ---------------- launcher ----------------
extern "C" void kernel_launch(void* const* d_in, const int* in_sizes, int n_in,
                              void* d_out, int out_size) {
    const float* x   = (const float*)d_in[0];
    const int*   row = (const int*)  d_in[1];
    const int*   col = (const int*)  d_in[2];
    const float* ew  = (const float*)d_in[3];
    const float* W1  = (const float*)d_in[4];
    const float* b1  = (const float*)d_in[5];
    const float* W2  = (const float*)d_in[6];
    const float* b2  = (const float*)d_in[7];

    const int E = in_sizes[1];
    const int G = in_sizes[0] / (2 * NN);

    cudaFuncSetAttribute(k_main, cudaFuncAttributeMaxDynamicSharedMemorySize, SMEM_BYTES);

    k_pre<<<1, 1024>>>(row, col, ew, E);
    k_main<<<G, TPB, SMEM_BYTES>>>(x, W1, b1, W2, b2, (float*)d_out);
}

// round 3
// speedup vs baseline: 1.2973x; 1.2973x over previous
#include <cuda_runtime.h>
#include <cuda_bf16.h>

// Fixed-shape problem: N=2000 nodes, F=2, HIDDEN=64, K=3, G=256 graphs, E~7998 edges
#define NN    2000
#define EMAX  20000
#define HID   64
#define TPB   512

typedef unsigned long long ull;

// ---------------- f32x2 packed-math helpers (sm_100+ PTX) ----------------
__device__ __forceinline__ ull pk2(float lo, float hi) {
    ull r; asm("mov.b64 %0,{%1,%2};" : "=l"(r) : "f"(lo), "f"(hi)); return r;
}
__device__ __forceinline__ void upk2(ull v, float& lo, float& hi) {
    asm("mov.b64 {%0,%1}, %2;" : "=f"(lo), "=f"(hi) : "l"(v));
}
__device__ __forceinline__ ull fma2v(ull a, ull b, ull c) {
    ull d; asm("fma.rn.f32x2 %0, %1, %2, %3;" : "=l"(d) : "l"(a), "l"(b), "l"(c)); return d;
}

// ---------------- device-global scratch ----------------
__device__ int  g_ptr[NN + 1];    // CSR row pointers (slot space, by destination)
__device__ int  g_perm[NN];       // perm[slot] = original node id
__device__ int2 g_edge[EMAX];     // .x = src slot, .y = bits of gcn_norm weight

// ---------------- fused prepass: one CTA, smem atomics + degree counting-sort ----------------
__global__ __launch_bounds__(1024)
void k_pre(const int* __restrict__ row, const int* __restrict__ col,
           const float* __restrict__ ew, int E) {
    __shared__ float sdeg[NN];       // weighted degree (node space)
    __shared__ int   scnt[NN];       // edge count (node space)
    __shared__ int   sinv[NN];       // node -> slot
    __shared__ int   sptr[NN + 1];   // CSR ptr (slot space)
    __shared__ int   scur[NN];       // scatter cursors / temp slot-degree
    __shared__ int   hist[64];
    __shared__ int   hoff[64];
    __shared__ int   warpsum[32];
    const int t = threadIdx.x;       // 1024 threads

    for (int i = t; i < NN; i += 1024) { sdeg[i] = 0.f; scnt[i] = 0; }
    if (t < 64) hist[t] = 0;
    __syncthreads();

    // weighted degree + per-dest counts
    for (int e = t; e < E; e += 1024) {
        int c = col[e];
        atomicAdd(&sdeg[c], ew[e]);
        atomicAdd(&scnt[c], 1);
    }
    __syncthreads();

    // degree histogram (cap at 63)
    for (int n = t; n < NN; n += 1024) {
        int d = scnt[n]; if (d > 63) d = 63;
        atomicAdd(&hist[d], 1);
    }
    __syncthreads();
    if (t == 0) {                    // exclusive scan over 64 bins
        int run = 0;
        for (int d = 0; d < 64; d++) { hoff[d] = run; run += hist[d]; }
    }
    __syncthreads();

    // assign slots (counting sort by degree), record perm / inv / slot-degree
    for (int n = t; n < NN; n += 1024) {
        int d = scnt[n]; int dc = (d > 63) ? 63 : d;
        int slot = atomicAdd(&hoff[dc], 1);
        sinv[n] = slot;
        g_perm[slot] = n;
        scur[slot] = d;              // slot-space degree (scan input)
    }
    __syncthreads();

    // exclusive scan of slot-degrees -> sptr / scur / g_ptr
    {
        int i0 = 2 * t, i1 = 2 * t + 1;
        int a0 = (i0 < NN) ? scur[i0] : 0;
        int a1 = (i1 < NN) ? scur[i1] : 0;
        int tot = a0 + a1;
        int lane = t & 31, wid = t >> 5;
        int v = tot;
        #pragma unroll
        for (int o = 1; o < 32; o <<= 1) {
            int u = __shfl_up_sync(0xFFFFFFFFu, v, o);
            if (lane >= o) v += u;
        }
        if (lane == 31) warpsum[wid] = v;
        __syncthreads();
        if (wid == 0) {
            int w = warpsum[lane];
            #pragma unroll
            for (int o = 1; o < 32; o <<= 1) {
                int u = __shfl_up_sync(0xFFFFFFFFu, w, o);
                if (lane >= o) w += u;
            }
            warpsum[lane] = w;
        }
        __syncthreads();
        int base = v - tot + (wid ? warpsum[wid - 1] : 0);
        if (i0 < NN) { sptr[i0] = base;      scur[i0] = base;      g_ptr[i0] = base; }
        if (i1 < NN) { sptr[i1] = base + a0; scur[i1] = base + a0; g_ptr[i1] = base + a0; }
        if (t == 0)  { sptr[NN] = E; g_ptr[NN] = E; }
    }
    __syncthreads();

    // scatter edges into slot-space CSR with precomputed gcn_norm weight
    for (int e = t; e < E; e += 1024) {
        int r = row[e], c = col[e];
        float dr = sdeg[r], dc = sdeg[c];
        float ir = (dr > 0.f) ? rsqrtf(dr) : 0.f;
        float ic = (dc > 0.f) ? rsqrtf(dc) : 0.f;
        float nrm = ir * ew[e] * ic;
        int p = atomicAdd(&scur[sinv[c]], 1);
        g_edge[p] = make_int2(sinv[r], __float_as_int(nrm));
    }
}

// ---------------- main fused kernel: one CTA per graph (slot space) ----------------
#define SMEM_BYTES (6 * NN * 8 + 2048 + 2048 + 256 + (NN + 1) * 4)

__device__ __forceinline__ void gather_hop(const ull* __restrict__ pin,
                                           ull* __restrict__ pout,
                                           const ull* __restrict__ addbuf,
                                           const int* __restrict__ sptr,
                                           int t, int bs) {
    for (int n = t; n < NN; n += bs) {
        int b = sptr[n], e = sptr[n + 1];
        ull acc = addbuf ? addbuf[n] : 0ull;     // 0 bits == (0.f, 0.f)
        for (int q = b; q < e; q++) {
            int2 ed = g_edge[q];
            float w = __int_as_float(ed.y);
            acc = fma2v(pin[ed.x], pk2(w, w), acc);
        }
        pout[n] = acc;
    }
}

__global__ __launch_bounds__(TPB, 2)
void k_main(const float* __restrict__ x,
            const float* __restrict__ W1, const float* __restrict__ b1,
            const float* __restrict__ W2, const float* __restrict__ b2,
            float* __restrict__ out) {
    extern __shared__ float sm[];
    ull* pb0     = (ull*)sm;
    ull* pb1     = pb0 + NN;
    ull* pb2     = pb1 + NN;
    ull* pb3     = pb2 + NN;
    ull* scratch = pb3 + NN;
    ull* xbuf    = scratch + NN;
    float* w1q = (float*)(xbuf + NN);    // [32 jp][8 i][2 half]
    float* w2q = w1q + 512;              // [32 jp][2 jj][8 c]
    float* b1s = w2q + 512;
    int*   sptr = (int*)(b1s + 64);

    const int t  = threadIdx.x;
    const int bs = blockDim.x;
    const int g  = blockIdx.x;

    // stage packed weights
    for (int i = t; i < 512; i += bs) {
        int jp = i >> 4, rem = i & 15;
        {   int ii = rem >> 1, half = rem & 1;
            w1q[i] = W1[ii * HID + 2 * jp + half]; }
        {   int jj = rem >> 3, c = rem & 7;
            int j = 2 * jp + jj;
            w2q[i] = W2[(c >> 1) * (HID * 2) + j * 2 + (c & 1)]; }
    }
    for (int i = t; i < HID; i += bs) b1s[i] = b1[i];
    for (int i = t; i < NN + 1; i += bs) sptr[i] = g_ptr[i];

    // stage x into slot space (permuted gather)
    const ull* xg = (const ull*)(x + (size_t)g * 2 * NN);
    for (int s = t; s < NN; s += bs) {
        int node = __ldg(&g_perm[s]);
        ull v = __ldg(&xg[node]);
        xbuf[s] = v; pb0[s] = v;
    }
    __syncthreads();

    // layer-1 hops: p_k = A p_{k-1}
    gather_hop(pb0, pb1, nullptr, sptr, t, bs); __syncthreads();
    gather_hop(pb1, pb2, nullptr, sptr, t, bs); __syncthreads();
    gather_hop(pb2, pb3, nullptr, sptr, t, bs); __syncthreads();

    // dense per-node sandwich: [8] -> 64 (relu) -> [8]; NPT=2 nodes share weight loads
    {
        const ulonglong2* w1v = (const ulonglong2*)w1q;   // 4 per jp
        const ulonglong2* w2v = (const ulonglong2*)w2q;   // 4 per jp
        const ull* b1v = (const ull*)b1s;
        #pragma unroll 1
        for (int half = 0; half < 2; half++) {
            int sA = t + half * 2 * TPB;
            int sB = sA + TPB;
            bool vA = (sA < NN), vB = (sB < NN);
            int iA = vA ? sA : 0, iB = vB ? sB : 0;
            float f0, f1; ull a;
            a = pb0[iA]; upk2(a, f0, f1); ull pA0 = pk2(f0, f0), pA1 = pk2(f1, f1);
            a = pb1[iA]; upk2(a, f0, f1); ull pA2 = pk2(f0, f0), pA3 = pk2(f1, f1);
            a = pb2[iA]; upk2(a, f0, f1); ull pA4 = pk2(f0, f0), pA5 = pk2(f1, f1);
            a = pb3[iA]; upk2(a, f0, f1); ull pA6 = pk2(f0, f0), pA7 = pk2(f1, f1);
            a = pb0[iB]; upk2(a, f0, f1); ull pB0 = pk2(f0, f0), pB1 = pk2(f1, f1);
            a = pb1[iB]; upk2(a, f0, f1); ull pB2 = pk2(f0, f0), pB3 = pk2(f1, f1);
            a = pb2[iB]; upk2(a, f0, f1); ull pB4 = pk2(f0, f0), pB5 = pk2(f1, f1);
            a = pb3[iB]; upk2(a, f0, f1); ull pB6 = pk2(f0, f0), pB7 = pk2(f1, f1);
            ull mA0 = 0, mA1 = 0, mA2 = 0, mA3 = 0;
            ull mB0 = 0, mB1 = 0, mB2 = 0, mB3 = 0;
            #pragma unroll 4
            for (int jp = 0; jp < 32; jp++) {
                ulonglong2 qa = w1v[jp * 4 + 0], qb = w1v[jp * 4 + 1];
                ulonglong2 qc = w1v[jp * 4 + 2], qd = w1v[jp * 4 + 3];
                ull bb = b1v[jp];
                ull hA = bb, hB = bb;
                hA = fma2v(pA0, qa.x, hA); hA = fma2v(pA1, qa.y, hA);
                hA = fma2v(pA2, qb.x, hA); hA = fma2v(pA3, qb.y, hA);
                hA = fma2v(pA4, qc.x, hA); hA = fma2v(pA5, qc.y, hA);
                hA = fma2v(pA6, qd.x, hA); hA = fma2v(pA7, qd.y, hA);
                hB = fma2v(pB0, qa.x, hB); hB = fma2v(pB1, qa.y, hB);
                hB = fma2v(pB2, qb.x, hB); hB = fma2v(pB3, qb.y, hB);
                hB = fma2v(pB4, qc.x, hB); hB = fma2v(pB5, qc.y, hB);
                hB = fma2v(pB6, qd.x, hB); hB = fma2v(pB7, qd.y, hB);
                float hA0, hA1, hB0, hB1;
                upk2(hA, hA0, hA1); upk2(hB, hB0, hB1);
                hA0 = fmaxf(hA0, 0.f); hA1 = fmaxf(hA1, 0.f);
                hB0 = fmaxf(hB0, 0.f); hB1 = fmaxf(hB1, 0.f);
                ull hA0p = pk2(hA0, hA0), hA1p = pk2(hA1, hA1);
                ull hB0p = pk2(hB0, hB0), hB1p = pk2(hB1, hB1);
                ulonglong2 ra = w2v[jp * 4 + 0], rb = w2v[jp * 4 + 1];
                ulonglong2 rc = w2v[jp * 4 + 2], rd = w2v[jp * 4 + 3];
                mA0 = fma2v(hA0p, ra.x, mA0); mA1 = fma2v(hA0p, ra.y, mA1);
                mA2 = fma2v(hA0p, rb.x, mA2); mA3 = fma2v(hA0p, rb.y, mA3);
                mA0 = fma2v(hA1p, rc.x, mA0); mA1 = fma2v(hA1p, rc.y, mA1);
                mA2 = fma2v(hA1p, rd.x, mA2); mA3 = fma2v(hA1p, rd.y, mA3);
                mB0 = fma2v(hB0p, ra.x, mB0); mB1 = fma2v(hB0p, ra.y, mB1);
                mB2 = fma2v(hB0p, rb.x, mB2); mB3 = fma2v(hB0p, rb.y, mB3);
                mB0 = fma2v(hB1p, rc.x, mB0); mB1 = fma2v(hB1p, rc.y, mB1);
                mB2 = fma2v(hB1p, rd.x, mB2); mB3 = fma2v(hB1p, rd.y, mB3);
            }
            if (vA) { pb0[sA] = mA0; pb1[sA] = mA1; pb2[sA] = mA2; pb3[sA] = mA3; }
            if (vB) { pb0[sB] = mB0; pb1[sB] = mB1; pb2[sB] = mB2; pb3[sB] = mB3; }
        }
    }
    __syncthreads();

    // layer-2 Horner: out2 = m0 + A(m1 + A(m2 + A m3))
    gather_hop(pb3, scratch, pb2, sptr, t, bs); __syncthreads();  // s = m2 + A m3
    gather_hop(scratch, pb3, pb1, sptr, t, bs); __syncthreads();  // s = m1 + A s

    // final: out = x + m0 + A s + b2 (scatter back through perm)
    float b20 = b2[0], b21 = b2[1];
    float2* og = (float2*)out + (size_t)g * NN;
    for (int s = t; s < NN; s += bs) {
        int b = sptr[s], e = sptr[s + 1];
        ull acc = pb0[s];
        for (int q = b; q < e; q++) {
            int2 ed = g_edge[q];
            float w = __int_as_float(ed.y);
            acc = fma2v(pb3[ed.x], pk2(w, w), acc);
        }
        float ox, oy; upk2(acc, ox, oy);
        float xl, xh; upk2(xbuf[s], xl, xh);
        int node = __ldg(&g_perm[s]);
        og[node] = make_float2(xl + ox + b20, xh + oy + b21);
    }
}

// ---------------- launcher ----------------
extern "C" void kernel_launch(void* const* d_in, const int* in_sizes, int n_in,
                              void* d_out, int out_size) {
    const float* x   = (const float*)d_in[0];
    const int*   row = (const int*)  d_in[1];
    const int*   col = (const int*)  d_in[2];
    const float* ew  = (const float*)d_in[3];
    const float* W1  = (const float*)d_in[4];
    const float* b1  = (const float*)d_in[5];
    const float* W2  = (const float*)d_in[6];
    const float* b2  = (const float*)d_in[7];

    const int E = in_sizes[1];
    const int G = in_sizes[0] / (2 * NN);

    cudaFuncSetAttribute(k_main, cudaFuncAttributeMaxDynamicSharedMemorySize, SMEM_BYTES);

    k_pre<<<1, 1024>>>(row, col, ew, E);
    k_main<<<G, TPB, SMEM_BYTES>>>(x, W1, b1, W2, b2, (float*)d_out);
}

// round 4
// speedup vs baseline: 1.3460x; 1.0376x over previous
#include <cuda_runtime.h>
#include <cuda_bf16.h>

// Fixed-shape problem: N=2000 nodes, F=2, HIDDEN=64, K=3, G=256 graphs, E~7998 edges
#define NN    2000
#define EMAX  20000
#define HID   64
#define TPB   1024

typedef unsigned long long ull;

// ---------------- f32x2 packed-math helpers (sm_100+ PTX) ----------------
__device__ __forceinline__ ull pk2(float lo, float hi) {
    ull r; asm("mov.b64 %0,{%1,%2};" : "=l"(r) : "f"(lo), "f"(hi)); return r;
}
__device__ __forceinline__ void upk2(ull v, float& lo, float& hi) {
    asm("mov.b64 {%0,%1}, %2;" : "=f"(lo), "=f"(hi) : "l"(v));
}
__device__ __forceinline__ ull fma2v(ull a, ull b, ull c) {
    ull d; asm("fma.rn.f32x2 %0, %1, %2, %3;" : "=l"(d) : "l"(a), "l"(b), "l"(c)); return d;
}

// ---------------- device-global scratch ----------------
__device__ int  g_ptr[NN + 1];    // CSR row pointers (slot space, by destination)
__device__ int  g_perm[NN];       // perm[slot] = original node id
__device__ int2 g_edge[EMAX];     // .x = src slot, .y = bits of gcn_norm weight

// ---------------- fused prepass: one CTA, smem atomics + degree counting-sort ----------------
__global__ __launch_bounds__(1024)
void k_pre(const int* __restrict__ row, const int* __restrict__ col,
           const float* __restrict__ ew, int E) {
    __shared__ float sdeg[NN];
    __shared__ int   scnt[NN];
    __shared__ int   sinv[NN];
    __shared__ int   sptr[NN + 1];
    __shared__ int   scur[NN];
    __shared__ int   hist[64];
    __shared__ int   hoff[64];
    __shared__ int   warpsum[32];
    const int t = threadIdx.x;

    for (int i = t; i < NN; i += 1024) { sdeg[i] = 0.f; scnt[i] = 0; }
    if (t < 64) hist[t] = 0;
    __syncthreads();

    for (int e = t; e < E; e += 1024) {
        int c = col[e];
        atomicAdd(&sdeg[c], ew[e]);
        atomicAdd(&scnt[c], 1);
    }
    __syncthreads();

    for (int n = t; n < NN; n += 1024) {
        int d = scnt[n]; if (d > 63) d = 63;
        atomicAdd(&hist[d], 1);
    }
    __syncthreads();
    if (t == 0) {
        int run = 0;
        for (int d = 0; d < 64; d++) { hoff[d] = run; run += hist[d]; }
    }
    __syncthreads();

    for (int n = t; n < NN; n += 1024) {
        int d = scnt[n]; int dc = (d > 63) ? 63 : d;
        int slot = atomicAdd(&hoff[dc], 1);
        sinv[n] = slot;
        g_perm[slot] = n;
        scur[slot] = d;
    }
    __syncthreads();

    {   // exclusive scan of slot-degrees -> sptr / scur / g_ptr
        int i0 = 2 * t, i1 = 2 * t + 1;
        int a0 = (i0 < NN) ? scur[i0] : 0;
        int a1 = (i1 < NN) ? scur[i1] : 0;
        int tot = a0 + a1;
        int lane = t & 31, wid = t >> 5;
        int v = tot;
        #pragma unroll
        for (int o = 1; o < 32; o <<= 1) {
            int u = __shfl_up_sync(0xFFFFFFFFu, v, o);
            if (lane >= o) v += u;
        }
        if (lane == 31) warpsum[wid] = v;
        __syncthreads();
        if (wid == 0) {
            int w = warpsum[lane];
            #pragma unroll
            for (int o = 1; o < 32; o <<= 1) {
                int u = __shfl_up_sync(0xFFFFFFFFu, w, o);
                if (lane >= o) w += u;
            }
            warpsum[lane] = w;
        }
        __syncthreads();
        int base = v - tot + (wid ? warpsum[wid - 1] : 0);
        if (i0 < NN) { sptr[i0] = base;      scur[i0] = base;      g_ptr[i0] = base; }
        if (i1 < NN) { sptr[i1] = base + a0; scur[i1] = base + a0; g_ptr[i1] = base + a0; }
        if (t == 0)  { sptr[NN] = E; g_ptr[NN] = E; }
    }
    __syncthreads();

    for (int e = t; e < E; e += 1024) {
        int r = row[e], c = col[e];
        float dr = sdeg[r], dc = sdeg[c];
        float ir = (dr > 0.f) ? rsqrtf(dr) : 0.f;
        float ic = (dc > 0.f) ? rsqrtf(dc) : 0.f;
        float nrm = ir * ew[e] * ic;
        int p = atomicAdd(&scur[sinv[c]], 1);
        g_edge[p] = make_int2(sinv[r], __float_as_int(nrm));
    }
}

// ---------------- main fused kernel: one CTA per TWO graphs (slot space) ----------------
// buffers hold {graphA pair, graphB pair} per node as ulonglong2 (16 B)
#define SMEM_BYTES (6 * NN * 16 + 2048 + 2048 + 256 + (NN + 1) * 4)

__device__ __forceinline__ void gather_hop2(const ulonglong2* __restrict__ pin,
                                            ulonglong2* __restrict__ pout,
                                            const ulonglong2* __restrict__ addbuf,
                                            const int* __restrict__ sptr,
                                            int t, int bs) {
    for (int n = t; n < NN; n += bs) {
        int b = sptr[n], e = sptr[n + 1];
        ull accA = 0ull, accB = 0ull;
        if (addbuf) { ulonglong2 a = addbuf[n]; accA = a.x; accB = a.y; }
        for (int q = b; q < e; q++) {
            int2 ed = g_edge[q];
            float w = __int_as_float(ed.y);
            ull ww = pk2(w, w);
            ulonglong2 v = pin[ed.x];
            accA = fma2v(v.x, ww, accA);
            accB = fma2v(v.y, ww, accB);
        }
        pout[n] = make_ulonglong2(accA, accB);
    }
}

__global__ __launch_bounds__(TPB, 1)
void k_main(const float* __restrict__ x,
            const float* __restrict__ W1, const float* __restrict__ b1,
            const float* __restrict__ W2, const float* __restrict__ b2,
            float* __restrict__ out, int G) {
    extern __shared__ float sm[];
    ulonglong2* pb0     = (ulonglong2*)sm;
    ulonglong2* pb1     = pb0 + NN;
    ulonglong2* pb2     = pb1 + NN;
    ulonglong2* pb3     = pb2 + NN;
    ulonglong2* scratch = pb3 + NN;
    ulonglong2* xbuf    = scratch + NN;
    float* w1q = (float*)(xbuf + NN);    // [32 jp][8 i][2 half]
    float* w2q = w1q + 512;              // [32 jp][2 jj][8 c]
    float* b1s = w2q + 512;
    int*   sptr = (int*)(b1s + 64);

    const int t  = threadIdx.x;
    const int bs = blockDim.x;
    const int gA = 2 * blockIdx.x;
    int gB = gA + 1; bool hasB = (gB < G); if (!hasB) gB = gA;

    // stage packed weights
    for (int i = t; i < 512; i += bs) {
        int jp = i >> 4, rem = i & 15;
        {   int ii = rem >> 1, half = rem & 1;
            w1q[i] = W1[ii * HID + 2 * jp + half]; }
        {   int jj = rem >> 3, c = rem & 7;
            int j = 2 * jp + jj;
            w2q[i] = W2[(c >> 1) * (HID * 2) + j * 2 + (c & 1)]; }
    }
    for (int i = t; i < HID; i += bs) b1s[i] = b1[i];
    for (int i = t; i < NN + 1; i += bs) sptr[i] = g_ptr[i];

    // stage x into slot space (permuted gather, both graphs)
    const ull* xgA = (const ull*)(x + (size_t)gA * 2 * NN);
    const ull* xgB = (const ull*)(x + (size_t)gB * 2 * NN);
    for (int s = t; s < NN; s += bs) {
        int node = __ldg(&g_perm[s]);
        ulonglong2 v = make_ulonglong2(__ldg(&xgA[node]), __ldg(&xgB[node]));
        xbuf[s] = v; pb0[s] = v;
    }
    __syncthreads();

    // layer-1 hops
    gather_hop2(pb0, pb1, nullptr, sptr, t, bs); __syncthreads();
    gather_hop2(pb1, pb2, nullptr, sptr, t, bs); __syncthreads();
    gather_hop2(pb2, pb3, nullptr, sptr, t, bs); __syncthreads();

    // dense per-node sandwich: [8] -> 64 (relu) -> [8]; both graphs share weight + p loads
    {
        const ulonglong2* w1v = (const ulonglong2*)w1q;
        const ulonglong2* w2v = (const ulonglong2*)w2q;
        const ull* b1v = (const ull*)b1s;
        for (int n = t; n < NN; n += bs) {
            ulonglong2 a0 = pb0[n], a1 = pb1[n], a2 = pb2[n], a3 = pb3[n];
            float f0, f1;
            upk2(a0.x, f0, f1); ull pA0 = pk2(f0, f0), pA1 = pk2(f1, f1);
            upk2(a1.x, f0, f1); ull pA2 = pk2(f0, f0), pA3 = pk2(f1, f1);
            upk2(a2.x, f0, f1); ull pA4 = pk2(f0, f0), pA5 = pk2(f1, f1);
            upk2(a3.x, f0, f1); ull pA6 = pk2(f0, f0), pA7 = pk2(f1, f1);
            upk2(a0.y, f0, f1); ull pB0 = pk2(f0, f0), pB1 = pk2(f1, f1);
            upk2(a1.y, f0, f1); ull pB2 = pk2(f0, f0), pB3 = pk2(f1, f1);
            upk2(a2.y, f0, f1); ull pB4 = pk2(f0, f0), pB5 = pk2(f1, f1);
            upk2(a3.y, f0, f1); ull pB6 = pk2(f0, f0), pB7 = pk2(f1, f1);
            ull mA0 = 0, mA1 = 0, mA2 = 0, mA3 = 0;
            ull mB0 = 0, mB1 = 0, mB2 = 0, mB3 = 0;
            #pragma unroll 4
            for (int jp = 0; jp < 32; jp++) {
                ulonglong2 qa = w1v[jp * 4 + 0], qb = w1v[jp * 4 + 1];
                ulonglong2 qc = w1v[jp * 4 + 2], qd = w1v[jp * 4 + 3];
                ull bb = b1v[jp];
                ull hA = bb, hB = bb;
                hA = fma2v(pA0, qa.x, hA); hA = fma2v(pA1, qa.y, hA);
                hA = fma2v(pA2, qb.x, hA); hA = fma2v(pA3, qb.y, hA);
                hA = fma2v(pA4, qc.x, hA); hA = fma2v(pA5, qc.y, hA);
                hA = fma2v(pA6, qd.x, hA); hA = fma2v(pA7, qd.y, hA);
                hB = fma2v(pB0, qa.x, hB); hB = fma2v(pB1, qa.y, hB);
                hB = fma2v(pB2, qb.x, hB); hB = fma2v(pB3, qb.y, hB);
                hB = fma2v(pB4, qc.x, hB); hB = fma2v(pB5, qc.y, hB);
                hB = fma2v(pB6, qd.x, hB); hB = fma2v(pB7, qd.y, hB);
                float hA0, hA1, hB0, hB1;
                upk2(hA, hA0, hA1); upk2(hB, hB0, hB1);
                hA0 = fmaxf(hA0, 0.f); hA1 = fmaxf(hA1, 0.f);
                hB0 = fmaxf(hB0, 0.f); hB1 = fmaxf(hB1, 0.f);
                ull hA0p = pk2(hA0, hA0), hA1p = pk2(hA1, hA1);
                ull hB0p = pk2(hB0, hB0), hB1p = pk2(hB1, hB1);
                ulonglong2 ra = w2v[jp * 4 + 0], rb = w2v[jp * 4 + 1];
                ulonglong2 rc = w2v[jp * 4 + 2], rd = w2v[jp * 4 + 3];
                mA0 = fma2v(hA0p, ra.x, mA0); mA1 = fma2v(hA0p, ra.y, mA1);
                mA2 = fma2v(hA0p, rb.x, mA2); mA3 = fma2v(hA0p, rb.y, mA3);
                mA0 = fma2v(hA1p, rc.x, mA0); mA1 = fma2v(hA1p, rc.y, mA1);
                mA2 = fma2v(hA1p, rd.x, mA2); mA3 = fma2v(hA1p, rd.y, mA3);
                mB0 = fma2v(hB0p, ra.x, mB0); mB1 = fma2v(hB0p, ra.y, mB1);
                mB2 = fma2v(hB0p, rb.x, mB2); mB3 = fma2v(hB0p, rb.y, mB3);
                mB0 = fma2v(hB1p, rc.x, mB0); mB1 = fma2v(hB1p, rc.y, mB1);
                mB2 = fma2v(hB1p, rd.x, mB2); mB3 = fma2v(hB1p, rd.y, mB3);
            }
            pb0[n] = make_ulonglong2(mA0, mB0);
            pb1[n] = make_ulonglong2(mA1, mB1);
            pb2[n] = make_ulonglong2(mA2, mB2);
            pb3[n] = make_ulonglong2(mA3, mB3);
        }
    }
    __syncthreads();

    // layer-2 Horner: out2 = m0 + A(m1 + A(m2 + A m3))
    gather_hop2(pb3, scratch, pb2, sptr, t, bs); __syncthreads();
    gather_hop2(scratch, pb3, pb1, sptr, t, bs); __syncthreads();

    // final: out = x + m0 + A s + b2 (scatter back through perm, both graphs)
    float b20 = b2[0], b21 = b2[1];
    float2* ogA = (float2*)out + (size_t)gA * NN;
    float2* ogB = (float2*)out + (size_t)gB * NN;
    for (int s = t; s < NN; s += bs) {
        int b = sptr[s], e = sptr[s + 1];
        ulonglong2 m0 = pb0[s];
        ull accA = m0.x, accB = m0.y;
        for (int q = b; q < e; q++) {
            int2 ed = g_edge[q];
            float w = __int_as_float(ed.y);
            ull ww = pk2(w, w);
            ulonglong2 v = pb3[ed.x];
            accA = fma2v(v.x, ww, accA);
            accB = fma2v(v.y, ww, accB);
        }
        ulonglong2 xv = xbuf[s];
        int node = __ldg(&g_perm[s]);
        float ox, oy, xl, xh;
        upk2(accA, ox, oy); upk2(xv.x, xl, xh);
        ogA[node] = make_float2(xl + ox + b20, xh + oy + b21);
        if (hasB) {
            upk2(accB, ox, oy); upk2(xv.y, xl, xh);
            ogB[node] = make_float2(xl + ox + b20, xh + oy + b21);
        }
    }
}

// ---------------- launcher ----------------
extern "C" void kernel_launch(void* const* d_in, const int* in_sizes, int n_in,
                              void* d_out, int out_size) {
    const float* x   = (const float*)d_in[0];
    const int*   row = (const int*)  d_in[1];
    const int*   col = (const int*)  d_in[2];
    const float* ew  = (const float*)d_in[3];
    const float* W1  = (const float*)d_in[4];
    const float* b1  = (const float*)d_in[5];
    const float* W2  = (const float*)d_in[6];
    const float* b2  = (const float*)d_in[7];

    const int E = in_sizes[1];
    const int G = in_sizes[0] / (2 * NN);
    const int nCta = (G + 1) / 2;

    cudaFuncSetAttribute(k_main, cudaFuncAttributeMaxDynamicSharedMemorySize, SMEM_BYTES);

    k_pre<<<1, 1024>>>(row, col, ew, E);
    k_main<<<nCta, TPB, SMEM_BYTES>>>(x, W1, b1, W2, b2, (float*)d_out, G);
}